// round 1
// baseline (speedup 1.0000x reference)
#include <cuda_runtime.h>

// NeuralNetwork_28819230556388 — B=262144 rows, D=64, chain of 7 targets:
//   out[1] = relu(h0 @ Wn0^T + bn0)
//   out[t] = relu(out[t-1] @ Wn[t-1]^T + bn[t-1]) + relu(out[t-2] @ Ws[t-2]^T + bs[t-2])
//   return out[7]
// Inputs (metadata order): x[B*64], Ws_next[8*64*64], bs_next[8*64],
//                          Ws_skip[7*64*64], bs_skip[7*64]. Output: float[B*64].
//
// Strategy: fp32x2-packed SIMT (FFMA2 via fma.rn.f32x2). 1 row/thread.
// Activations ping-pong in padded SMEM (conflict-free), weights staged per
// layer into SMEM transposed+packed over output pairs.

#define TPB   256          // threads per block = rows per block
#define HPAD  65           // padded row length (bank-conflict-free)
#define NBLK  (262144 / TPB)

typedef unsigned long long u64;

// ---- SMEM layout (bytes) ----
#define OFF_HB0   0                         // 256*65*4 = 66560
#define OFF_HB1   66560                     // 66560
#define OFF_WPN   133120                    // 2048 * 8 = 16384 (16B aligned)
#define OFF_WPS   149504                    // 16384
#define OFF_BN2   165888                    // 256
#define OFF_BS2   166144                    // 256
#define OFF_RAW   166400                    // 64*65*4 = 16640
#define SMEM_BYTES 183040

__device__ __forceinline__ u64 pk2(float lo, float hi) {
    u64 r;
    asm("mov.b64 %0, {%1, %2};" : "=l"(r) : "f"(lo), "f"(hi));
    return r;
}
__device__ __forceinline__ void unpk2(u64 v, float& lo, float& hi) {
    asm("mov.b64 {%0, %1}, %2;" : "=f"(lo), "=f"(hi) : "l"(v));
}
// Packed fp32x2 FMA (Blackwell FFMA2): d = a*b + c on both 32-bit lanes.
__device__ __forceinline__ u64 ffma2(u64 a, u64 b, u64 c) {
    u64 d;
    asm("fma.rn.f32x2 %0, %1, %2, %3;" : "=l"(d) : "l"(a), "l"(b), "l"(c));
    return d;
}

// Stage one 64x64 weight matrix: global (row-major W[j][k]) -> SMEM packed
// WP[k*32 + j2] = (W[2*j2][k], W[2*j2+1][k]).
// Two passes through a padded raw buffer keep global reads coalesced and all
// SMEM accesses (nearly) conflict-free.
__device__ __forceinline__ void stage_pack(const float* __restrict__ Wg,
                                           u64* __restrict__ WP,
                                           float* __restrict__ raw)
{
    const int tid = threadIdx.x;
#pragma unroll 4
    for (int idx = tid; idx < 4096; idx += TPB) {
        int j = idx >> 6, k = idx & 63;
        raw[j * HPAD + k] = Wg[idx];            // coalesced read, cf-free write
    }
    __syncthreads();                             // also guards WP vs prior compute
#pragma unroll 2
    for (int idx = tid; idx < 2048; idx += TPB) {
        int j2 = idx & 31, k = idx >> 5;         // WP[idx] == WP[k*32 + j2]
        WP[idx] = pk2(raw[(2 * j2) * HPAD + k],
                      raw[(2 * j2 + 1) * HPAD + k]);   // 2-way conflict only
    }
    __syncthreads();
}

// One 64x64 matvec for this thread's row: newh[j] (+)= relu(h . W^T + b)[j]
template <bool ACC>
__device__ __forceinline__ void matvec64(const float* __restrict__ hrow,
                                         const u64* __restrict__ WP,
                                         const u64* __restrict__ b2,
                                         float* __restrict__ newh)
{
    u64 acc[32];
#pragma unroll
    for (int i = 0; i < 32; ++i) acc[i] = b2[i];

#pragma unroll 8
    for (int k = 0; k < 64; ++k) {
        float hv = hrow[k];                      // LDS.32, conflict-free (pad 65)
        u64 h2 = pk2(hv, hv);
        const ulonglong2* wk =
            reinterpret_cast<const ulonglong2*>(WP + (k << 5)); // uniform LDS.128
#pragma unroll
        for (int i = 0; i < 16; ++i) {
            ulonglong2 w = wk[i];
            acc[2 * i]     = ffma2(h2, w.x, acc[2 * i]);
            acc[2 * i + 1] = ffma2(h2, w.y, acc[2 * i + 1]);
        }
    }
#pragma unroll
    for (int i = 0; i < 32; ++i) {
        float lo, hi;
        unpk2(acc[i], lo, hi);
        lo = fmaxf(lo, 0.0f);
        hi = fmaxf(hi, 0.0f);
        if (ACC) { newh[2 * i] += lo; newh[2 * i + 1] += hi; }
        else     { newh[2 * i]  = lo; newh[2 * i + 1]  = hi; }
    }
}

__global__ void __launch_bounds__(TPB, 1)
nn_chain_kernel(const float* __restrict__ x,
                const float* __restrict__ Wn_g,
                const float* __restrict__ bn_g,
                const float* __restrict__ Ws_g,
                const float* __restrict__ bs_g,
                float* __restrict__ out)
{
    extern __shared__ unsigned char sm[];
    float* hb[2] = { reinterpret_cast<float*>(sm + OFF_HB0),
                     reinterpret_cast<float*>(sm + OFF_HB1) };
    u64*   WPn = reinterpret_cast<u64*>(sm + OFF_WPN);
    u64*   WPs = reinterpret_cast<u64*>(sm + OFF_WPS);
    u64*   bn2 = reinterpret_cast<u64*>(sm + OFF_BN2);
    u64*   bs2 = reinterpret_cast<u64*>(sm + OFF_BS2);
    float* raw = reinterpret_cast<float*>(sm + OFF_RAW);

    const int tid = threadIdx.x;
    const long long row0 = (long long)blockIdx.x * TPB;

    // Load x tile (coalesced) into hb[0]; visibility guaranteed by the
    // barriers inside the first stage_pack below.
    const float* xg = x + row0 * 64;
#pragma unroll 4
    for (int idx = tid; idx < TPB * 64; idx += TPB) {
        int r = idx >> 6, k = idx & 63;
        hb[0][r * HPAD + k] = xg[idx];
    }

    float newh[64];
    int p = 0;   // hb[p] = h_{t-1}, hb[1-p] = h_{t-2}

    for (int t = 1; t <= 7; ++t) {
        stage_pack(Wn_g + (t - 1) * 4096, WPn, raw);
        if (t >= 2) stage_pack(Ws_g + (t - 2) * 4096, WPs, raw);
        if (tid < 32) {
            bn2[tid] = pk2(bn_g[(t - 1) * 64 + 2 * tid],
                           bn_g[(t - 1) * 64 + 2 * tid + 1]);
            if (t >= 2)
                bs2[tid] = pk2(bs_g[(t - 2) * 64 + 2 * tid],
                               bs_g[(t - 2) * 64 + 2 * tid + 1]);
        }
        __syncthreads();

        const float* prow = hb[p] + tid * HPAD;
        matvec64<false>(prow, WPn, bn2, newh);
        if (t >= 2) {
            const float* p2row = hb[1 - p] + tid * HPAD;
            matvec64<true>(p2row, WPs, bs2, newh);
        }
        // Rotate: new h overwrites the retired h_{t-2} buffer (own row only,
        // no cross-thread hazard -> no barrier needed here).
        float* drow = hb[1 - p] + tid * HPAD;
#pragma unroll
        for (int k = 0; k < 64; ++k) drow[k] = newh[k];
        p ^= 1;
    }

    __syncthreads();   // final buffer is read across threads for coalesced store
    float* og = out + row0 * 64;
#pragma unroll 4
    for (int idx = tid; idx < TPB * 64; idx += TPB) {
        int r = idx >> 6, k = idx & 63;
        og[idx] = hb[p][r * HPAD + k];
    }
}

extern "C" void kernel_launch(void* const* d_in, const int* in_sizes, int n_in,
                              void* d_out, int out_size)
{
    const float* x  = (const float*)d_in[0];
    const float* Wn = (const float*)d_in[1];
    const float* bn = (const float*)d_in[2];
    const float* Ws = (const float*)d_in[3];
    const float* bs = (const float*)d_in[4];
    float* out = (float*)d_out;

    cudaFuncSetAttribute(nn_chain_kernel,
                         cudaFuncAttributeMaxDynamicSharedMemorySize, SMEM_BYTES);
    nn_chain_kernel<<<NBLK, TPB, SMEM_BYTES>>>(x, Wn, bn, Ws, bs, out);
}

// round 2
// speedup vs baseline: 1.0003x; 1.0003x over previous
#include <cuda_runtime.h>

// NeuralNetwork_28819230556388 — B=262144 rows, D=64, chain of 7 targets:
//   out[1] = relu(h0 @ Wn0^T + bn0)
//   out[t] = relu(out[t-1] @ Wn[t-1]^T + bn[t-1]) + relu(out[t-2] @ Ws[t-2]^T + bs[t-2])
//   return out[7]
// Inputs (metadata order): x[B*64], Ws_next[8*64*64], bs_next[8*64],
//                          Ws_skip[7*64*64], bs_skip[7*64]. Output: float[B*64].
//
// Strategy: fp32x2-packed SIMT (FFMA2 via fma.rn.f32x2). 1 row/thread.
// Activations ping-pong in padded SMEM (conflict-free), weights staged per
// layer into SMEM transposed+packed over output pairs.

#define TPB   256          // threads per block = rows per block
#define HPAD  65           // padded row length (bank-conflict-free)
#define NBLK  (262144 / TPB)

typedef unsigned long long u64;

// ---- SMEM layout (bytes) ----
#define OFF_HB0   0                         // 256*65*4 = 66560
#define OFF_HB1   66560                     // 66560
#define OFF_WPN   133120                    // 2048 * 8 = 16384 (16B aligned)
#define OFF_WPS   149504                    // 16384
#define OFF_BN2   165888                    // 256
#define OFF_BS2   166144                    // 256
#define OFF_RAW   166400                    // 64*65*4 = 16640
#define SMEM_BYTES 183040

__device__ __forceinline__ u64 pk2(float lo, float hi) {
    u64 r;
    asm("mov.b64 %0, {%1, %2};" : "=l"(r) : "f"(lo), "f"(hi));
    return r;
}
__device__ __forceinline__ void unpk2(u64 v, float& lo, float& hi) {
    asm("mov.b64 {%0, %1}, %2;" : "=f"(lo), "=f"(hi) : "l"(v));
}
// Packed fp32x2 FMA (Blackwell FFMA2): d = a*b + c on both 32-bit lanes.
__device__ __forceinline__ u64 ffma2(u64 a, u64 b, u64 c) {
    u64 d;
    asm("fma.rn.f32x2 %0, %1, %2, %3;" : "=l"(d) : "l"(a), "l"(b), "l"(c));
    return d;
}

// Stage one 64x64 weight matrix: global (row-major W[j][k]) -> SMEM packed
// WP[k*32 + j2] = (W[2*j2][k], W[2*j2+1][k]).
// Two passes through a padded raw buffer keep global reads coalesced and all
// SMEM accesses (nearly) conflict-free.
__device__ __forceinline__ void stage_pack(const float* __restrict__ Wg,
                                           u64* __restrict__ WP,
                                           float* __restrict__ raw)
{
    const int tid = threadIdx.x;
#pragma unroll 4
    for (int idx = tid; idx < 4096; idx += TPB) {
        int j = idx >> 6, k = idx & 63;
        raw[j * HPAD + k] = Wg[idx];            // coalesced read, cf-free write
    }
    __syncthreads();                             // also guards WP vs prior compute
#pragma unroll 2
    for (int idx = tid; idx < 2048; idx += TPB) {
        int j2 = idx & 31, k = idx >> 5;         // WP[idx] == WP[k*32 + j2]
        WP[idx] = pk2(raw[(2 * j2) * HPAD + k],
                      raw[(2 * j2 + 1) * HPAD + k]);   // 2-way conflict only
    }
    __syncthreads();
}

// One 64x64 matvec for this thread's row: newh[j] (+)= relu(h . W^T + b)[j]
template <bool ACC>
__device__ __forceinline__ void matvec64(const float* __restrict__ hrow,
                                         const u64* __restrict__ WP,
                                         const u64* __restrict__ b2,
                                         float* __restrict__ newh)
{
    u64 acc[32];
#pragma unroll
    for (int i = 0; i < 32; ++i) acc[i] = b2[i];

#pragma unroll 8
    for (int k = 0; k < 64; ++k) {
        float hv = hrow[k];                      // LDS.32, conflict-free (pad 65)
        u64 h2 = pk2(hv, hv);
        const ulonglong2* wk =
            reinterpret_cast<const ulonglong2*>(WP + (k << 5)); // uniform LDS.128
#pragma unroll
        for (int i = 0; i < 16; ++i) {
            ulonglong2 w = wk[i];
            acc[2 * i]     = ffma2(h2, w.x, acc[2 * i]);
            acc[2 * i + 1] = ffma2(h2, w.y, acc[2 * i + 1]);
        }
    }
#pragma unroll
    for (int i = 0; i < 32; ++i) {
        float lo, hi;
        unpk2(acc[i], lo, hi);
        lo = fmaxf(lo, 0.0f);
        hi = fmaxf(hi, 0.0f);
        if (ACC) { newh[2 * i] += lo; newh[2 * i + 1] += hi; }
        else     { newh[2 * i]  = lo; newh[2 * i + 1]  = hi; }
    }
}

__global__ void __launch_bounds__(TPB, 1)
nn_chain_kernel(const float* __restrict__ x,
                const float* __restrict__ Wn_g,
                const float* __restrict__ bn_g,
                const float* __restrict__ Ws_g,
                const float* __restrict__ bs_g,
                float* __restrict__ out)
{
    extern __shared__ unsigned char sm[];
    float* hb[2] = { reinterpret_cast<float*>(sm + OFF_HB0),
                     reinterpret_cast<float*>(sm + OFF_HB1) };
    u64*   WPn = reinterpret_cast<u64*>(sm + OFF_WPN);
    u64*   WPs = reinterpret_cast<u64*>(sm + OFF_WPS);
    u64*   bn2 = reinterpret_cast<u64*>(sm + OFF_BN2);
    u64*   bs2 = reinterpret_cast<u64*>(sm + OFF_BS2);
    float* raw = reinterpret_cast<float*>(sm + OFF_RAW);

    const int tid = threadIdx.x;
    const long long row0 = (long long)blockIdx.x * TPB;

    // Load x tile (coalesced) into hb[0]; visibility guaranteed by the
    // barriers inside the first stage_pack below.
    const float* xg = x + row0 * 64;
#pragma unroll 4
    for (int idx = tid; idx < TPB * 64; idx += TPB) {
        int r = idx >> 6, k = idx & 63;
        hb[0][r * HPAD + k] = xg[idx];
    }

    float newh[64];
    int p = 0;   // hb[p] = h_{t-1}, hb[1-p] = h_{t-2}

    for (int t = 1; t <= 7; ++t) {
        stage_pack(Wn_g + (t - 1) * 4096, WPn, raw);
        if (t >= 2) stage_pack(Ws_g + (t - 2) * 4096, WPs, raw);
        if (tid < 32) {
            bn2[tid] = pk2(bn_g[(t - 1) * 64 + 2 * tid],
                           bn_g[(t - 1) * 64 + 2 * tid + 1]);
            if (t >= 2)
                bs2[tid] = pk2(bs_g[(t - 2) * 64 + 2 * tid],
                               bs_g[(t - 2) * 64 + 2 * tid + 1]);
        }
        __syncthreads();

        const float* prow = hb[p] + tid * HPAD;
        matvec64<false>(prow, WPn, bn2, newh);
        if (t >= 2) {
            const float* p2row = hb[1 - p] + tid * HPAD;
            matvec64<true>(p2row, WPs, bs2, newh);
        }
        // Rotate: new h overwrites the retired h_{t-2} buffer (own row only,
        // no cross-thread hazard -> no barrier needed here).
        float* drow = hb[1 - p] + tid * HPAD;
#pragma unroll
        for (int k = 0; k < 64; ++k) drow[k] = newh[k];
        p ^= 1;
    }

    __syncthreads();   // final buffer is read across threads for coalesced store
    float* og = out + row0 * 64;
#pragma unroll 4
    for (int idx = tid; idx < TPB * 64; idx += TPB) {
        int r = idx >> 6, k = idx & 63;
        og[idx] = hb[p][r * HPAD + k];
    }
}

extern "C" void kernel_launch(void* const* d_in, const int* in_sizes, int n_in,
                              void* d_out, int out_size)
{
    const float* x  = (const float*)d_in[0];
    const float* Wn = (const float*)d_in[1];
    const float* bn = (const float*)d_in[2];
    const float* Ws = (const float*)d_in[3];
    const float* bs = (const float*)d_in[4];
    float* out = (float*)d_out;

    cudaFuncSetAttribute(nn_chain_kernel,
                         cudaFuncAttributeMaxDynamicSharedMemorySize, SMEM_BYTES);
    nn_chain_kernel<<<NBLK, TPB, SMEM_BYTES>>>(x, Wn, bn, Ws, bs, out);
}

// round 4
// speedup vs baseline: 4.4202x; 4.4189x over previous
#include <cuda_runtime.h>
#include <cuda_bf16.h>
#include <cstdint>

// NeuralNetwork_28819230556388 — B=262144, D=64, 13 chained 64x64 GEMMs.
// mma.sync.m16n8k16 bf16 (arch-agnostic HMMA; tcgen05 is blocked: harness PTX
// target is compute_103, no 'a'). bf16 hi/lo 3-product split for fp32-grade
// accuracy. Activations live entirely in registers (C-frag == A-frag layout),
// weights resident in SMEM, persistent CTAs, zero barriers in the main loop.

#define TPB    256
#define GRID   148
#define NTILES 2048

// SMEM layout (bytes)
#define OFF_BN 0                     // 7*64 f32 = 1792
#define OFF_BS 1792                  // 6*64 f32 = 1536
#define OFF_W  4096                  // 26 half-matrices * 8192 (hi at +0, lo at +8192 per mat)
#define SMEM_TOTAL (4096 + 26*8192)  // 217088

#define SMEM_SWIZZLE_128B(bo) ((bo) ^ (((bo) >> 3) & 0x70))

__device__ __forceinline__ uint32_t smem_to_u32(const void* p) {
    uint32_t a;
    asm("{ .reg .u64 t; cvta.to.shared.u64 t, %1; cvt.u32.u64 %0, t; }"
        : "=r"(a) : "l"(p));
    return a;
}

// ldmatrix x4 (non-trans): 4 8x8 b16 tiles; W stored [n][k] row-major gives
// exactly the row.col B-fragment (n = t/4, k-pairs along register halves).
#define LDSM_X4(r, addr) \
    asm volatile("ldmatrix.sync.aligned.m8n8.x4.shared.b16 {%0,%1,%2,%3}, [%4];" \
        : "=r"((r)[0]), "=r"((r)[1]), "=r"((r)[2]), "=r"((r)[3]) \
        : "r"(addr))

__device__ __forceinline__ void mma_bf16(float d[4], const uint32_t a[4],
                                         uint32_t b0, uint32_t b1) {
    asm volatile(
        "mma.sync.aligned.m16n8k16.row.col.f32.bf16.bf16.f32 "
        "{%0,%1,%2,%3}, {%4,%5,%6,%7}, {%8,%9}, {%0,%1,%2,%3};"
        : "+f"(d[0]), "+f"(d[1]), "+f"(d[2]), "+f"(d[3])
        : "r"(a[0]), "r"(a[1]), "r"(a[2]), "r"(a[3]), "r"(b0), "r"(b1));
}

// split (a,b) into bf16 hi pair + bf16 residual pair (packed b32, a in low half)
__device__ __forceinline__ void pack_split(float a, float b,
                                           uint32_t& hi, uint32_t& lo) {
    __nv_bfloat162 h = __floats2bfloat162_rn(a, b);
    float ra = a - __bfloat162float(h.x);
    float rb = b - __bfloat162float(h.y);
    __nv_bfloat162 l = __floats2bfloat162_rn(ra, rb);
    hi = *reinterpret_cast<uint32_t*>(&h);
    lo = *reinterpret_cast<uint32_t*>(&l);
}

// activation fragment for one warp's 16 rows x 64 cols: hi/lo bf16 A-frags,
// [ktile][reg] (a0: row g, k+0..1; a1: row g+8; a2: row g, k+8..9; a3: row g+8)
struct Frag {
    uint32_t h[4][4];
    uint32_t l[4][4];
};

// One layer: An = relu(Ap @ Wn^T + bn) [+ relu(Ap2 @ Ws^T + bs)]
// wn/ws = SMEM addr of hi half (lo at +8192). LAST: store fp32 to gmem instead.
template <bool HAS_SKIP, bool LAST>
__device__ __forceinline__ void layer_step(
    const Frag& Ap, const Frag& Ap2, Frag& An,
    uint32_t wn, uint32_t ws,
    const float* __restrict__ bnp, const float* __restrict__ bsp,
    uint32_t soff0, uint32_t soff1, int qt,
    float* __restrict__ out0, float* __restrict__ out1)
{
#pragma unroll
    for (int np = 0; np < 4; ++np) {        // n-tile pair: nts 2np, 2np+1
        float dn[2][4], ds[2][4];
#pragma unroll
        for (int i2 = 0; i2 < 2; ++i2)
#pragma unroll
            for (int r = 0; r < 4; ++r) { dn[i2][r] = 0.0f; ds[i2][r] = 0.0f; }

        uint32_t Bn[2][8], Bs[2][8];
        // phase A/B weights: Wn.hi (and Ws.hi)
#pragma unroll
        for (int i2 = 0; i2 < 2; ++i2) {
            uint32_t a = wn + (uint32_t)(2 * np + i2) * 1024;
            LDSM_X4(&Bn[i2][0], a + soff0);
            LDSM_X4(&Bn[i2][4], a + soff1);
            if (HAS_SKIP) {
                uint32_t s = ws + (uint32_t)(2 * np + i2) * 1024;
                LDSM_X4(&Bs[i2][0], s + soff0);
                LDSM_X4(&Bs[i2][4], s + soff1);
            }
        }
        // phase A: A.hi x W.hi   (4 independent chains with skip)
#pragma unroll
        for (int kt = 0; kt < 4; ++kt)
#pragma unroll
            for (int i2 = 0; i2 < 2; ++i2) {
                mma_bf16(dn[i2], Ap.h[kt], Bn[i2][2 * kt], Bn[i2][2 * kt + 1]);
                if (HAS_SKIP)
                    mma_bf16(ds[i2], Ap2.h[kt], Bs[i2][2 * kt], Bs[i2][2 * kt + 1]);
            }
        // phase B: A.lo x W.hi
#pragma unroll
        for (int kt = 0; kt < 4; ++kt)
#pragma unroll
            for (int i2 = 0; i2 < 2; ++i2) {
                mma_bf16(dn[i2], Ap.l[kt], Bn[i2][2 * kt], Bn[i2][2 * kt + 1]);
                if (HAS_SKIP)
                    mma_bf16(ds[i2], Ap2.l[kt], Bs[i2][2 * kt], Bs[i2][2 * kt + 1]);
            }
        // phase C weights: Wn.lo (and Ws.lo), reuse registers
#pragma unroll
        for (int i2 = 0; i2 < 2; ++i2) {
            uint32_t a = wn + 8192u + (uint32_t)(2 * np + i2) * 1024;
            LDSM_X4(&Bn[i2][0], a + soff0);
            LDSM_X4(&Bn[i2][4], a + soff1);
            if (HAS_SKIP) {
                uint32_t s = ws + 8192u + (uint32_t)(2 * np + i2) * 1024;
                LDSM_X4(&Bs[i2][0], s + soff0);
                LDSM_X4(&Bs[i2][4], s + soff1);
            }
        }
        // phase C: A.hi x W.lo
#pragma unroll
        for (int kt = 0; kt < 4; ++kt)
#pragma unroll
            for (int i2 = 0; i2 < 2; ++i2) {
                mma_bf16(dn[i2], Ap.h[kt], Bn[i2][2 * kt], Bn[i2][2 * kt + 1]);
                if (HAS_SKIP)
                    mma_bf16(ds[i2], Ap2.h[kt], Bs[i2][2 * kt], Bs[i2][2 * kt + 1]);
            }

        // epilogue: bias + relu (+skip), then C-frag -> next A-frag (pure regs)
#pragma unroll
        for (int i2 = 0; i2 < 2; ++i2) {
            const int nt = 2 * np + i2;
            float b0 = bnp[8 * nt + 2 * qt];
            float b1 = bnp[8 * nt + 2 * qt + 1];
            float v0 = fmaxf(dn[i2][0] + b0, 0.0f);
            float v1 = fmaxf(dn[i2][1] + b1, 0.0f);
            float v2 = fmaxf(dn[i2][2] + b0, 0.0f);
            float v3 = fmaxf(dn[i2][3] + b1, 0.0f);
            if (HAS_SKIP) {
                float s0 = bsp[8 * nt + 2 * qt];
                float s1 = bsp[8 * nt + 2 * qt + 1];
                v0 += fmaxf(ds[i2][0] + s0, 0.0f);
                v1 += fmaxf(ds[i2][1] + s1, 0.0f);
                v2 += fmaxf(ds[i2][2] + s0, 0.0f);
                v3 += fmaxf(ds[i2][3] + s1, 0.0f);
            }
            if (LAST) {
                float2* p0 = reinterpret_cast<float2*>(out0 + 8 * nt + 2 * qt);
                float2* p1 = reinterpret_cast<float2*>(out1 + 8 * nt + 2 * qt);
                *p0 = make_float2(v0, v1);
                *p1 = make_float2(v2, v3);
            } else {
                // ktile = np; nt even -> a0,a1; nt odd -> a2,a3
                pack_split(v0, v1, An.h[np][2 * i2],     An.l[np][2 * i2]);
                pack_split(v2, v3, An.h[np][2 * i2 + 1], An.l[np][2 * i2 + 1]);
            }
        }
    }
}

__global__ void __launch_bounds__(TPB, 1)
nn_mma_kernel(const float* __restrict__ x,
              const float* __restrict__ Wn_g,
              const float* __restrict__ bn_g,
              const float* __restrict__ Ws_g,
              const float* __restrict__ bs_g,
              float* __restrict__ out)
{
    extern __shared__ unsigned char sm[];
    const uint32_t smb = smem_to_u32(sm);
    const int tid  = threadIdx.x;
    const int wid  = tid >> 5;
    const int lane = tid & 31;
    const int qt   = lane & 3;          // col-pair id
    const int grp  = lane >> 2;         // row group 0..7

    // ---- stage 13 weight matrices as bf16 hi/lo, [n][k] row-major, SW128 ----
    for (int idx = tid; idx < 13 * 4096; idx += TPB) {
        int mat = idx >> 12, e = idx & 4095;
        float v = (mat < 7) ? Wn_g[mat * 4096 + e] : Ws_g[(mat - 7) * 4096 + e];
        __nv_bfloat16 hb = __float2bfloat16(v);
        __nv_bfloat16 lb = __float2bfloat16(v - __bfloat162float(hb));
        int n = e >> 6, k = e & 63;
        uint32_t sw = SMEM_SWIZZLE_128B((uint32_t)(n * 128 + k * 2));
        uint32_t base = OFF_W + (uint32_t)mat * 16384;
        *reinterpret_cast<__nv_bfloat16*>(sm + base + sw)        = hb;
        *reinterpret_cast<__nv_bfloat16*>(sm + base + 8192 + sw) = lb;
    }
    for (int i = tid; i < 448; i += TPB)
        reinterpret_cast<float*>(sm + OFF_BN)[i] = bn_g[i];
    for (int i = tid; i < 384; i += TPB)
        reinterpret_cast<float*>(sm + OFF_BS)[i] = bs_g[i];
    __syncthreads();

    // per-thread ldmatrix.x4 swizzled offsets (kh = 0/1 covers ktiles 0-1 / 2-3)
    const int r8 = lane & 7, b4 = lane >> 3;
    const uint32_t soff0 = (uint32_t)(r8 * 128 + ((b4 * 16)      ^ (r8 * 16)));
    const uint32_t soff1 = (uint32_t)(r8 * 128 + ((b4 * 16 + 64) ^ (r8 * 16)));

    const float* bn = reinterpret_cast<const float*>(sm + OFF_BN);
    const float* bs = reinterpret_cast<const float*>(sm + OFF_BS);
    const uint32_t w0 = smb + OFF_W;

    const int row0 = wid * 16 + grp;    // this thread's rows within the tile
    const int row1 = row0 + 8;

    for (int tile = blockIdx.x; tile < NTILES; tile += GRID) {
        const size_t gr0 = (size_t)tile * 128 + row0;
        const size_t gr1 = (size_t)tile * 128 + row1;

        Frag A0, A1, A2;

        // ---- load x -> A-frag (hi/lo) directly from gmem ----
        {
            const float* xr0 = x + gr0 * 64;
            const float* xr1 = x + gr1 * 64;
#pragma unroll
            for (int kt = 0; kt < 4; ++kt) {
                const int c = 16 * kt + 2 * qt;
                float2 p0 = *reinterpret_cast<const float2*>(xr0 + c);
                float2 p1 = *reinterpret_cast<const float2*>(xr1 + c);
                float2 p2 = *reinterpret_cast<const float2*>(xr0 + c + 8);
                float2 p3 = *reinterpret_cast<const float2*>(xr1 + c + 8);
                pack_split(p0.x, p0.y, A0.h[kt][0], A0.l[kt][0]);
                pack_split(p1.x, p1.y, A0.h[kt][1], A0.l[kt][1]);
                pack_split(p2.x, p2.y, A0.h[kt][2], A0.l[kt][2]);
                pack_split(p3.x, p3.y, A0.h[kt][3], A0.l[kt][3]);
            }
        }

        float* o0 = out + gr0 * 64;
        float* o1 = out + gr1 * 64;

        // slots: h_t lives in S[t%3]; layer t reads S[(t-1)%3], S[(t-2)%3]
        layer_step<false, false>(A0, A0, A1, w0 + 0 * 16384, 0,
                                 bn + 0 * 64, bs, soff0, soff1, qt, o0, o1);
        layer_step<true,  false>(A1, A0, A2, w0 + 1 * 16384, w0 + 7 * 16384,
                                 bn + 1 * 64, bs + 0 * 64, soff0, soff1, qt, o0, o1);
        layer_step<true,  false>(A2, A1, A0, w0 + 2 * 16384, w0 + 8 * 16384,
                                 bn + 2 * 64, bs + 1 * 64, soff0, soff1, qt, o0, o1);
        layer_step<true,  false>(A0, A2, A1, w0 + 3 * 16384, w0 + 9 * 16384,
                                 bn + 3 * 64, bs + 2 * 64, soff0, soff1, qt, o0, o1);
        layer_step<true,  false>(A1, A0, A2, w0 + 4 * 16384, w0 + 10 * 16384,
                                 bn + 4 * 64, bs + 3 * 64, soff0, soff1, qt, o0, o1);
        layer_step<true,  false>(A2, A1, A0, w0 + 5 * 16384, w0 + 11 * 16384,
                                 bn + 5 * 64, bs + 4 * 64, soff0, soff1, qt, o0, o1);
        layer_step<true,  true >(A0, A2, A1, w0 + 6 * 16384, w0 + 12 * 16384,
                                 bn + 6 * 64, bs + 5 * 64, soff0, soff1, qt, o0, o1);
    }
}

extern "C" void kernel_launch(void* const* d_in, const int* in_sizes, int n_in,
                              void* d_out, int out_size)
{
    const float* x  = (const float*)d_in[0];
    const float* Wn = (const float*)d_in[1];
    const float* bn = (const float*)d_in[2];
    const float* Ws = (const float*)d_in[3];
    const float* bs = (const float*)d_in[4];
    float* out = (float*)d_out;

    cudaFuncSetAttribute(nn_mma_kernel,
                         cudaFuncAttributeMaxDynamicSharedMemorySize, SMEM_TOTAL);
    nn_mma_kernel<<<GRID, TPB, SMEM_TOTAL>>>(x, Wn, bn, Ws, bs, out);
}